// round 7
// baseline (speedup 1.0000x reference)
#include <cuda_runtime.h>

#define LOG2E 1.4426950408889634f
#define LN2   0.6931471805599453f
#define CHUNK 128
#define MAXC  8          // ceil(1023/128)
#define NTASK 16         // 0..7 = q (backward), 8..14 = r (forward), 15 = gathers

__device__ float g_qv[1024][MAXC][64];
__device__ float g_rv[1024][MAXC - 1][64];
__device__ float g_qoff[1024][MAXC];
__device__ float g_roff[1024][MAXC - 1];
__device__ float g_seqs[1024];
__device__ float g_partial[1024];
__device__ unsigned int g_done[1024];   // zero-init; self-resetting
__device__ unsigned int g_count = 0;

static __device__ __forceinline__ float ex2f_(float x) {
    float y; asm("ex2.approx.ftz.f32 %0, %1;" : "=f"(y) : "f"(x)); return y;
}
static __device__ __forceinline__ float lg2f_(float x) {
    float y; asm("lg2.approx.ftz.f32 %0, %1;" : "=f"(y) : "f"(x)); return y;
}
static __device__ __forceinline__ unsigned long long pack2_(float lo, float hi) {
    unsigned long long d;
    asm("mov.b64 %0, {%1, %2};" : "=l"(d) : "f"(lo), "f"(hi));
    return d;
}
static __device__ __forceinline__ unsigned long long fma2_(unsigned long long a,
                                                           unsigned long long b,
                                                           unsigned long long c) {
    unsigned long long d;
    asm("fma.rn.f32x2 %0, %1, %2, %3;" : "=l"(d) : "l"(a), "l"(b), "l"(c));
    return d;
}
static __device__ __forceinline__ unsigned long long addx2_(unsigned long long a,
                                                            unsigned long long b) {
    unsigned long long d;
    asm("add.rn.f32x2 %0, %1, %2;" : "=l"(d) : "l"(a), "l"(b));
    return d;
}
static __device__ __forceinline__ void unpack2_(unsigned long long v, float& lo, float& hi) {
    asm("mov.b64 {%0, %1}, %2;" : "=f"(lo), "=f"(hi) : "l"(v));
}
static __device__ __forceinline__ float wredsum_(float v) {
#pragma unroll
    for (int m = 16; m > 0; m >>= 1) v += __shfl_xor_sync(0xffffffffu, v, m);
    return v;
}

// Load w once (16 broadcast LDS.128), contract against BOTH columns eA, eB.
#define MAC64x2(BUF, SA, SB)                                                \
    {                                                                       \
        const ulonglong2* wv_ = (const ulonglong2*)(BUF);                   \
        unsigned long long a0_=0ull,a1_=0ull,a2_=0ull,a3_=0ull;             \
        unsigned long long b0_=0ull,b1_=0ull,b2_=0ull,b3_=0ull;             \
        _Pragma("unroll")                                                   \
        for (int k_ = 0; k_ < 8; k_++) {                                    \
            ulonglong2 q0_ = wv_[2 * k_];                                   \
            ulonglong2 q1_ = wv_[2 * k_ + 1];                               \
            a0_ = fma2_(q0_.x, eA[4*k_+0], a0_);                            \
            b0_ = fma2_(q0_.x, eB[4*k_+0], b0_);                            \
            a1_ = fma2_(q0_.y, eA[4*k_+1], a1_);                            \
            b1_ = fma2_(q0_.y, eB[4*k_+1], b1_);                            \
            a2_ = fma2_(q1_.x, eA[4*k_+2], a2_);                            \
            b2_ = fma2_(q1_.x, eB[4*k_+2], b2_);                            \
            a3_ = fma2_(q1_.y, eA[4*k_+3], a3_);                            \
            b3_ = fma2_(q1_.y, eB[4*k_+3], b3_);                            \
        }                                                                   \
        float lo_, hi_;                                                     \
        unpack2_(addx2_(addx2_(a0_,a2_), addx2_(a1_,a3_)), lo_, hi_);       \
        SA = lo_ + hi_;                                                     \
        unpack2_(addx2_(addx2_(b0_,b2_), addx2_(b1_,b3_)), lo_, hi_);       \
        SB = lo_ + hi_;                                                     \
    }

// forward: read wsh[CUR], write wsh[CUR^1]; Dreg = previous step's w[0]
#define STEPF(UU, CUR, NORM)                                                \
    {                                                                       \
        float pA_, pB_;                                                     \
        if (NORM) {                                                         \
            float lD_ = lg2f_(Dreg); loff += lD_;                           \
            pA_ = ex2f_(fmaf(pfA[UU], LOG2E, -lD_));                        \
            pB_ = ex2f_(fmaf(pfB[UU], LOG2E, -lD_));                        \
        } else {                                                            \
            pA_ = ex2f_(pfA[UU] * LOG2E);                                   \
            pB_ = ex2f_(pfB[UU] * LOG2E);                                   \
        }                                                                   \
        pfA[UU] = *(const float*)(potc + off);                              \
        pfB[UU] = *(const float*)(potc + off + 128);                        \
        off = min(off + 256, offmax);                                       \
        float sA_, sB_;                                                     \
        MAC64x2(&wsh[CUR][0], sA_, sB_)                                     \
        float vA_ = sA_ * pA_, vB_ = sB_ * pB_;                             \
        wsh[(CUR) ^ 1][lane]      = vA_;                                    \
        wsh[(CUR) ^ 1][lane + 32] = vB_;                                    \
        Dreg = __shfl_sync(0xffffffffu, vA_, 0);                            \
        __syncwarp();                                                       \
    }

// backward: y = p*x into wsh[CUR]; x <- E y; Dreg = previous step's y[0]
#define STEPB(UU, CUR, NORM)                                                \
    {                                                                       \
        float pA_, pB_;                                                     \
        if (NORM) {                                                         \
            float lD_ = lg2f_(Dreg); loff += lD_;                           \
            pA_ = ex2f_(fmaf(pfA[UU], LOG2E, -lD_));                        \
            pB_ = ex2f_(fmaf(pfB[UU], LOG2E, -lD_));                        \
        } else {                                                            \
            pA_ = ex2f_(pfA[UU] * LOG2E);                                   \
            pB_ = ex2f_(pfB[UU] * LOG2E);                                   \
        }                                                                   \
        pfA[UU] = *(const float*)(potc + off);                              \
        pfB[UU] = *(const float*)(potc + off + 128);                        \
        off = max(off - 256, offmin);                                       \
        float yA_ = pA_ * xA, yB_ = pB_ * xB;                               \
        wsh[CUR][lane]      = yA_;                                          \
        wsh[CUR][lane + 32] = yB_;                                          \
        Dreg = __shfl_sync(0xffffffffu, yA_, 0);                            \
        __syncwarp();                                                       \
        MAC64x2(&wsh[CUR][0], xA, xB)                                       \
    }

// One CTA (ONE WARP) per (batch, task). Lane handles states lane and lane+32.
__global__ __launch_bounds__(32, 1) void crf_all_kernel(
    const float* __restrict__ pot,     // [B, T, 64]
    const int*   __restrict__ tags,    // [B, T]
    const int*   __restrict__ seqlen,  // [B]
    const float* __restrict__ K,       // [64, 64]
    const float* __restrict__ sw,      // [B]
    float*       __restrict__ out,
    int T, int B)
{
    const int b    = blockIdx.x / NTASK;
    const int k    = blockIdx.x % NTASK;
    const int lane = threadIdx.x;

    int L = seqlen[b];
    if (L > T) L = T;
    if (L < 1) L = 1;
    const int M  = L - 1;
    const int nc = (M + CHUNK - 1) / CHUNK;

    const float* potb = pot + (size_t)b * T * 64;
    const char*  potc = (const char*)potb;

    __shared__ __align__(16) float wsh[2][64];
    __shared__ int stags[1024];

    if (k == 15) {
        // ================= sequence-score gathers =================
        const int* tagb = tags + (size_t)b * T;
        for (int t = lane; t < T; t += 32) stags[t] = tagb[t];
        __syncwarp();
        float acc = 0.f;
        for (int t = lane; t < T; t += 32) {
            if (t < L) {
                int tg = stags[t];
                acc += __ldg(potb + (size_t)t * 64 + tg);
                if (t >= 1) acc += __ldg(K + stags[t - 1] * 64 + tg);
            }
        }
        acc = wredsum_(acc);
        if (lane == 0) g_seqs[b] = acc;
    } else {
        const bool is_q = (k < MAXC);
        const int  c    = is_q ? (k + 1) : (k - MAXC + 1);
        const bool valid = is_q ? (c <= nc) : (c <= nc - 1);
        if (!valid) return;    // invalid tasks do NOT arrive

        const int a    = (c - 1) * CHUNK + 1;
        const int bend = min(c * CHUNK, M);
        const int ns   = bend - a + 1;

        // E registers: two columns (forward) or two rows (backward)
        unsigned long long eA[32], eB[32];
        if (is_q) {
#pragma unroll
            for (int m = 0; m < 32; m++) {
                eA[m] = pack2_(ex2f_(K[lane * 64 + 2*m]       * LOG2E),
                               ex2f_(K[lane * 64 + 2*m + 1]   * LOG2E));
                eB[m] = pack2_(ex2f_(K[(lane+32) * 64 + 2*m]     * LOG2E),
                               ex2f_(K[(lane+32) * 64 + 2*m + 1] * LOG2E));
            }
        } else {
#pragma unroll
            for (int m = 0; m < 32; m++) {
                eA[m] = pack2_(ex2f_(K[(2*m) * 64 + lane]       * LOG2E),
                               ex2f_(K[(2*m + 1) * 64 + lane]   * LOG2E));
                eB[m] = pack2_(ex2f_(K[(2*m) * 64 + lane + 32]     * LOG2E),
                               ex2f_(K[(2*m + 1) * 64 + lane + 32] * LOG2E));
            }
        }

        float loff = 0.f, Dreg = 1.0f;
        float pfA[4], pfB[4];

        if (is_q) {
            // ---- backward: x = Pi_{t=a..bend} (E diag p_t) * 1 ----
            float xA = 1.0f, xB = 1.0f;
#pragma unroll
            for (int u = 0; u < 4; u++) {
                int r = bend - u; if (r < a) r = a;
                pfA[u] = potb[(size_t)r * 64 + lane];
                pfB[u] = potb[(size_t)r * 64 + lane + 32];
            }
            const int offmin = a * 256 + (lane << 2);
            int off = (bend - 4) * 256 + (lane << 2);
            if (off < offmin) off = offmin;

            int n4 = ns >> 2;
            for (int it = 0; it < n4; it++) {
                STEPB(0, 0, 0) STEPB(1, 1, 1) STEPB(2, 0, 0) STEPB(3, 1, 1)
            }
            int rem = ns & 3;
            if (rem > 0) STEPB(0, 0, 0)
            if (rem > 1) STEPB(1, 1, 1)
            if (rem > 2) STEPB(2, 0, 0)

            g_qv[b][c - 1][lane]      = xA;
            g_qv[b][c - 1][lane + 32] = xB;
            if (lane == 0) g_qoff[b][c - 1] = loff;
        } else {
            // ---- forward: r^T = 1^T Pi_{t=a..bend} (E diag p_t) ----
            wsh[0][lane] = 1.0f;
            wsh[0][lane + 32] = 1.0f;
            __syncwarp();
#pragma unroll
            for (int u = 0; u < 4; u++) {
                int r = a + u; if (r > bend) r = bend;
                pfA[u] = potb[(size_t)r * 64 + lane];
                pfB[u] = potb[(size_t)r * 64 + lane + 32];
            }
            const int offmax = bend * 256 + (lane << 2);
            int off = (a + 4) * 256 + (lane << 2);
            if (off > offmax) off = offmax;

            int n4 = ns >> 2;
            for (int it = 0; it < n4; it++) {
                STEPF(0, 0, 0) STEPF(1, 1, 1) STEPF(2, 0, 0) STEPF(3, 1, 1)
            }
            int rem = ns & 3;
            if (rem > 0) STEPF(0, 0, 0)
            if (rem > 1) STEPF(1, 1, 1)
            if (rem > 2) STEPF(2, 0, 0)

            g_rv[b][c - 1][lane]      = wsh[ns & 1][lane];
            g_rv[b][c - 1][lane + 32] = wsh[ns & 1][lane + 32];
            if (lane == 0) g_roff[b][c - 1] = loff;
        }
    }

    // ================= arrival + inline stitch (last task of batch) =================
    __threadfence();
    unsigned int old = 0;
    if (lane == 0) old = atomicAdd(&g_done[b], 1);
    old = __shfl_sync(0xffffffffu, old, 0);
    const unsigned int ntasks = 1u + (unsigned)nc + (unsigned)(nc > 0 ? nc - 1 : 0);
    if (old != ntasks - 1) return;

    if (lane == 0) g_done[b] = 0;    // reset for graph replay
    __threadfence();

    float p0lo = ex2f_(potb[lane] * LOG2E);
    float p0hi = ex2f_(potb[lane + 32] * LOG2E);

    float log2A;
    if (nc == 0) {
        log2A = lg2f_(wredsum_(p0lo + p0hi));
    } else {
        float d1 = wredsum_(p0lo * g_qv[b][0][lane] + p0hi * g_qv[b][0][lane + 32]);
        log2A = lg2f_(d1) + g_qoff[b][0];
        for (int cc = 2; cc <= nc; cc++) {
            float d = wredsum_(g_rv[b][cc-2][lane]      * g_qv[b][cc-1][lane] +
                               g_rv[b][cc-2][lane + 32] * g_qv[b][cc-1][lane + 32]);
            float sig = wredsum_(g_qv[b][cc-2][lane] + g_qv[b][cc-2][lane + 32]);
            log2A += lg2f_(d) + g_roff[b][cc-2] + g_qoff[b][cc-1]
                   - lg2f_(sig) - g_qoff[b][cc-2];
        }
    }

    if (lane == 0) {
        g_partial[b] = -(g_seqs[b] - log2A * LN2) * sw[b];
        __threadfence();
    }
    __syncwarp();

    unsigned int o2 = 0;
    if (lane == 0) o2 = atomicAdd(&g_count, 1);
    o2 = __shfl_sync(0xffffffffu, o2, 0);
    if (o2 == (unsigned)B - 1) {
        if (lane == 0) { g_count = 0; __threadfence(); }
        __syncwarp();
        float tot = 0.f;
        for (int i = lane; i < B; i += 32) tot += g_partial[i];
        tot = wredsum_(tot);
        if (lane == 0) *out = tot / (float)B;
    }
}

extern "C" void kernel_launch(void* const* d_in, const int* in_sizes, int n_in,
                              void* d_out, int out_size) {
    const float* pot    = (const float*)d_in[0];
    const int*   tags   = (const int*)d_in[1];
    const int*   seqlen = (const int*)d_in[2];
    const float* K      = (const float*)d_in[3];
    const float* sw     = (const float*)d_in[4];

    int B = in_sizes[2];            // sequence_length element count
    int T = in_sizes[1] / B;        // tags is [B, T]

    crf_all_kernel<<<B * NTASK, 32>>>(pot, tags, seqlen, K, sw, (float*)d_out, T, B);
}

// round 8
// speedup vs baseline: 1.0290x; 1.0290x over previous
#include <cuda_runtime.h>

#define LOG2E 1.4426950408889634f
#define LN2   0.6931471805599453f
#define CHUNK 128
#define MAXC  8          // ceil(1023/128)
#define NTASK 16         // 0..7 = q (backward), 8..14 = r (forward), 15 = gathers

__device__ float g_qv[1024][MAXC][64];
__device__ float g_rv[1024][MAXC - 1][64];
__device__ float g_qoff[1024][MAXC];
__device__ float g_roff[1024][MAXC - 1];
__device__ float g_seqs[1024];
__device__ float g_partial[1024];
__device__ unsigned int g_done[1024];   // zero-init; self-resetting
__device__ unsigned int g_count = 0;

static __device__ __forceinline__ float ex2f_(float x) {
    float y; asm("ex2.approx.ftz.f32 %0, %1;" : "=f"(y) : "f"(x)); return y;
}
static __device__ __forceinline__ float lg2f_(float x) {
    float y; asm("lg2.approx.ftz.f32 %0, %1;" : "=f"(y) : "f"(x)); return y;
}
static __device__ __forceinline__ unsigned long long pack2_(float lo, float hi) {
    unsigned long long d;
    asm("mov.b64 %0, {%1, %2};" : "=l"(d) : "f"(lo), "f"(hi));
    return d;
}
static __device__ __forceinline__ unsigned long long fma2_(unsigned long long a,
                                                           unsigned long long b,
                                                           unsigned long long c) {
    unsigned long long d;
    asm("fma.rn.f32x2 %0, %1, %2, %3;" : "=l"(d) : "l"(a), "l"(b), "l"(c));
    return d;
}
static __device__ __forceinline__ unsigned long long addx2_(unsigned long long a,
                                                            unsigned long long b) {
    unsigned long long d;
    asm("add.rn.f32x2 %0, %1, %2;" : "=l"(d) : "l"(a), "l"(b));
    return d;
}
static __device__ __forceinline__ void unpack2_(unsigned long long v, float& lo, float& hi) {
    asm("mov.b64 {%0, %1}, %2;" : "=f"(lo), "=f"(hi) : "l"(v));
}
static __device__ __forceinline__ float wredsum_(float v) {
#pragma unroll
    for (int m = 16; m > 0; m >>= 1) v += __shfl_xor_sync(0xffffffffu, v, m);
    return v;
}

// Contract this warp's i-half (32 i's) for both states: 32 FFMA2/thread.
#define MACH(SA, SB)                                                        \
    {                                                                       \
        const ulonglong2* wv_ = (const ulonglong2*)(&wsh[h << 5]);          \
        unsigned long long a0_=0ull, a1_=0ull, b0_=0ull, b1_=0ull;          \
        _Pragma("unroll")                                                   \
        for (int k_ = 0; k_ < 8; k_++) {                                    \
            ulonglong2 q_ = wv_[k_];                                        \
            a0_ = fma2_(q_.x, eA[2*k_],     a0_);                           \
            a1_ = fma2_(q_.y, eA[2*k_ + 1], a1_);                           \
            b0_ = fma2_(q_.x, eB[2*k_],     b0_);                           \
            b1_ = fma2_(q_.y, eB[2*k_ + 1], b1_);                           \
        }                                                                   \
        float lo_, hi_;                                                     \
        unpack2_(addx2_(a0_, a1_), lo_, hi_); SA = lo_ + hi_;               \
        unpack2_(addx2_(b0_, b1_), lo_, hi_); SB = lo_ + hi_;               \
    }

// One recurrence body: MAC both halves; warp1 posts partials; warp0 combines,
// applies p (renorm every 2nd body), stores next vector. Two cheap nw=2 BARs.
#define BODY(UU, NORM)                                                      \
    {                                                                       \
        float sA_, sB_;                                                     \
        MACH(sA_, sB_)                                                      \
        if (h) pp[lane] = make_float2(sA_, sB_);                            \
        __syncthreads();                                                    \
        if (h == 0) {                                                       \
            float2 q_ = pp[lane];                                           \
            float zA_ = sA_ + q_.x, zB_ = sB_ + q_.y;                       \
            float pA_, pB_;                                                 \
            if (NORM) {                                                     \
                float lD_ = lg2f_(Dreg); loff += lD_;                       \
                pA_ = ex2f_(fmaf(pfA[UU], LOG2E, -lD_));                    \
                pB_ = ex2f_(fmaf(pfB[UU], LOG2E, -lD_));                    \
            } else {                                                        \
                pA_ = ex2f_(pfA[UU] * LOG2E);                               \
                pB_ = ex2f_(pfB[UU] * LOG2E);                               \
            }                                                               \
            pfA[UU] = *(const float*)(potc + off);                          \
            pfB[UU] = *(const float*)(potc + off + 128);                    \
            off = min(max(off + dstep, offlo), offhi);                      \
            float vA_ = zA_ * pA_, vB_ = zB_ * pB_;                         \
            wsh[lane]      = vA_;                                           \
            wsh[lane + 32] = vB_;                                           \
            Dreg = __shfl_sync(0xffffffffu, vA_, 0);                        \
        }                                                                   \
        __syncthreads();                                                    \
    }

// One CTA (64 threads, 2 warps) per (batch, task).
// lane = states (lane, lane+32); warp h owns i-range [32h, 32h+32).
__global__ __launch_bounds__(64, 8) void crf_all_kernel(
    const float* __restrict__ pot,     // [B, T, 64]
    const int*   __restrict__ tags,    // [B, T]
    const int*   __restrict__ seqlen,  // [B]
    const float* __restrict__ K,       // [64, 64]
    const float* __restrict__ sw,      // [B]
    float*       __restrict__ out,
    int T, int B)
{
    const int b    = blockIdx.x / NTASK;
    const int k    = blockIdx.x % NTASK;
    const int tid  = threadIdx.x;
    const int lane = tid & 31;
    const int h    = tid >> 5;

    int L = seqlen[b];
    if (L > T) L = T;
    if (L < 1) L = 1;
    const int M  = L - 1;
    const int nc = (M + CHUNK - 1) / CHUNK;

    const float* potb = pot + (size_t)b * T * 64;
    const char*  potc = (const char*)potb;

    __shared__ __align__(16) float wsh[64];
    __shared__ float2 pp[64];
    __shared__ float sred[64];
    __shared__ int stags[1024];

    if (k == 15) {
        // ================= sequence-score gathers =================
        const int* tagb = tags + (size_t)b * T;
        for (int t = tid; t < T; t += 64) stags[t] = tagb[t];
        __syncthreads();
        float acc = 0.f;
        for (int t = tid; t < T; t += 64) {
            if (t < L) {
                int tg = stags[t];
                acc += __ldg(potb + (size_t)t * 64 + tg);
                if (t >= 1) acc += __ldg(K + stags[t - 1] * 64 + tg);
            }
        }
        sred[tid] = acc;
        __syncthreads();
        if (h == 0) {
            float v = sred[lane] + sred[lane + 32];
            v = wredsum_(v);
            if (lane == 0) g_seqs[b] = v;
        }
    } else {
        const bool is_q = (k < MAXC);
        const int  c    = is_q ? (k + 1) : (k - MAXC + 1);
        const bool valid = is_q ? (c <= nc) : (c <= nc - 1);
        if (!valid) return;    // invalid tasks do NOT arrive

        const int a    = (c - 1) * CHUNK + 1;
        const int bend = min(c * CHUNK, M);
        const int ns   = bend - a + 1;
        const int lane4 = lane << 2;

        // E registers: this warp's i-half, both states.
        unsigned long long eA[16], eB[16];
        if (is_q) {
#pragma unroll
            for (int m = 0; m < 16; m++) {
                int i0 = (h << 5) + 2 * m;
                eA[m] = pack2_(ex2f_(K[lane * 64 + i0]     * LOG2E),
                               ex2f_(K[lane * 64 + i0 + 1] * LOG2E));
                eB[m] = pack2_(ex2f_(K[(lane + 32) * 64 + i0]     * LOG2E),
                               ex2f_(K[(lane + 32) * 64 + i0 + 1] * LOG2E));
            }
        } else {
#pragma unroll
            for (int m = 0; m < 16; m++) {
                int i0 = (h << 5) + 2 * m;
                eA[m] = pack2_(ex2f_(K[i0 * 64 + lane]       * LOG2E),
                               ex2f_(K[(i0 + 1) * 64 + lane] * LOG2E));
                eB[m] = pack2_(ex2f_(K[i0 * 64 + lane + 32]       * LOG2E),
                               ex2f_(K[(i0 + 1) * 64 + lane + 32] * LOG2E));
            }
        }

        float loff = 0.f, Dreg = 1.0f;
        float pfA[4], pfB[4];
        const int offlo = a * 256 + lane4;
        const int offhi = bend * 256 + lane4;

        if (is_q) {
            // ---- backward: q = Pi_{t=a..bend} (E diag p_t) * 1 ----
            // prologue: y_bend = p_bend
            if (h == 0) {
                float pA0 = ex2f_(potb[(size_t)bend * 64 + lane]      * LOG2E);
                float pB0 = ex2f_(potb[(size_t)bend * 64 + lane + 32] * LOG2E);
                wsh[lane]      = pA0;
                wsh[lane + 32] = pB0;
                Dreg = __shfl_sync(0xffffffffu, pA0, 0);
#pragma unroll
                for (int u = 0; u < 4; u++) {
                    int r = bend - 1 - u; if (r < a) r = a;
                    pfA[u] = potb[(size_t)r * 64 + lane];
                    pfB[u] = potb[(size_t)r * 64 + lane + 32];
                }
            }
            __syncthreads();
            const int dstep = -256;
            int off = (bend - 5) * 256 + lane4;
            if (off < offlo) off = offlo;

            const int nb = ns - 1;           // bodies handle t = bend-1 .. a
            int n4 = nb >> 2;
            for (int it = 0; it < n4; it++) {
                BODY(0, 1) BODY(1, 0) BODY(2, 1) BODY(3, 0)
            }
            int rem = nb & 3;
            if (rem > 0) BODY(0, 1)
            if (rem > 1) BODY(1, 0)
            if (rem > 2) BODY(2, 1)

            // epilogue: final MAC (no p) + combine -> q
            float sA_, sB_;
            MACH(sA_, sB_)
            if (h) pp[lane] = make_float2(sA_, sB_);
            __syncthreads();
            if (h == 0) {
                float2 q_ = pp[lane];
                g_qv[b][c - 1][lane]      = sA_ + q_.x;
                g_qv[b][c - 1][lane + 32] = sB_ + q_.y;
                if (lane == 0) g_qoff[b][c - 1] = loff;
            }
        } else {
            // ---- forward: r = diag(p_bend) E^T ... diag(p_a) E^T * 1 ----
            if (h == 0) {
                wsh[lane]      = 1.0f;
                wsh[lane + 32] = 1.0f;
#pragma unroll
                for (int u = 0; u < 4; u++) {
                    int r = a + u; if (r > bend) r = bend;
                    pfA[u] = potb[(size_t)r * 64 + lane];
                    pfB[u] = potb[(size_t)r * 64 + lane + 32];
                }
            }
            __syncthreads();
            const int dstep = 256;
            int off = (a + 4) * 256 + lane4;
            if (off > offhi) off = offhi;

            int n4 = ns >> 2;
            for (int it = 0; it < n4; it++) {
                BODY(0, 0) BODY(1, 1) BODY(2, 0) BODY(3, 1)
            }
            int rem = ns & 3;
            if (rem > 0) BODY(0, 0)
            if (rem > 1) BODY(1, 1)
            if (rem > 2) BODY(2, 0)

            if (h == 0) {
                g_rv[b][c - 1][lane]      = wsh[lane];
                g_rv[b][c - 1][lane + 32] = wsh[lane + 32];
                if (lane == 0) g_roff[b][c - 1] = loff;
            }
        }
    }

    // ================= arrival + inline stitch (warp 0 only) =================
    if (h != 0) return;
    __threadfence();
    unsigned int old = 0;
    if (lane == 0) old = atomicAdd(&g_done[b], 1);
    old = __shfl_sync(0xffffffffu, old, 0);
    const unsigned int ntasks = 1u + (unsigned)nc + (unsigned)(nc > 0 ? nc - 1 : 0);
    if (old != ntasks - 1) return;

    if (lane == 0) g_done[b] = 0;    // reset for graph replay
    __threadfence();

    float p0lo = ex2f_(potb[lane] * LOG2E);
    float p0hi = ex2f_(potb[lane + 32] * LOG2E);

    float log2A;
    if (nc == 0) {
        log2A = lg2f_(wredsum_(p0lo + p0hi));
    } else {
        float d1 = wredsum_(p0lo * g_qv[b][0][lane] + p0hi * g_qv[b][0][lane + 32]);
        log2A = lg2f_(d1) + g_qoff[b][0];
        for (int cc = 2; cc <= nc; cc++) {
            float d = wredsum_(g_rv[b][cc-2][lane]      * g_qv[b][cc-1][lane] +
                               g_rv[b][cc-2][lane + 32] * g_qv[b][cc-1][lane + 32]);
            float sig = wredsum_(g_qv[b][cc-2][lane] + g_qv[b][cc-2][lane + 32]);
            log2A += lg2f_(d) + g_roff[b][cc-2] + g_qoff[b][cc-1]
                   - lg2f_(sig) - g_qoff[b][cc-2];
        }
    }

    if (lane == 0) {
        g_partial[b] = -(g_seqs[b] - log2A * LN2) * sw[b];
        __threadfence();
    }
    __syncwarp();

    unsigned int o2 = 0;
    if (lane == 0) o2 = atomicAdd(&g_count, 1);
    o2 = __shfl_sync(0xffffffffu, o2, 0);
    if (o2 == (unsigned)B - 1) {
        if (lane == 0) { g_count = 0; __threadfence(); }
        __syncwarp();
        float tot = 0.f;
        for (int i = lane; i < B; i += 32) tot += g_partial[i];
        tot = wredsum_(tot);
        if (lane == 0) *out = tot / (float)B;
    }
}

extern "C" void kernel_launch(void* const* d_in, const int* in_sizes, int n_in,
                              void* d_out, int out_size) {
    const float* pot    = (const float*)d_in[0];
    const int*   tags   = (const int*)d_in[1];
    const int*   seqlen = (const int*)d_in[2];
    const float* K      = (const float*)d_in[3];
    const float* sw     = (const float*)d_in[4];

    int B = in_sizes[2];            // sequence_length element count
    int T = in_sizes[1] / B;        // tags is [B, T]

    crf_all_kernel<<<B * NTASK, 64>>>(pot, tags, seqlen, K, sw, (float*)d_out, T, B);
}

// round 9
// speedup vs baseline: 1.0349x; 1.0058x over previous
#include <cuda_runtime.h>

#define LOG2E 1.4426950408889634f
#define LN2   0.6931471805599453f
#define CHUNK 128
#define MAXC  8          // ceil(1023/128)
#define NTASK 16         // 0..7 = q (backward), 8..14 = r (forward), 15 = gathers

__device__ float g_qv[1024][MAXC][64];
__device__ float g_rv[1024][MAXC - 1][64];
__device__ float g_qoff[1024][MAXC];
__device__ float g_roff[1024][MAXC - 1];
__device__ float g_seqs[1024];
__device__ float g_partial[1024];
__device__ unsigned int g_done[1024];   // zero-init; self-resetting
__device__ unsigned int g_count = 0;

static __device__ __forceinline__ float ex2f_(float x) {
    float y; asm("ex2.approx.ftz.f32 %0, %1;" : "=f"(y) : "f"(x)); return y;
}
static __device__ __forceinline__ float lg2f_(float x) {
    float y; asm("lg2.approx.ftz.f32 %0, %1;" : "=f"(y) : "f"(x)); return y;
}
static __device__ __forceinline__ unsigned long long pack2_(float lo, float hi) {
    unsigned long long d;
    asm("mov.b64 %0, {%1, %2};" : "=l"(d) : "f"(lo), "f"(hi));
    return d;
}
static __device__ __forceinline__ unsigned long long fma2_(unsigned long long a,
                                                           unsigned long long b,
                                                           unsigned long long c) {
    unsigned long long d;
    asm("fma.rn.f32x2 %0, %1, %2, %3;" : "=l"(d) : "l"(a), "l"(b), "l"(c));
    return d;
}
static __device__ __forceinline__ unsigned long long addx2_(unsigned long long a,
                                                            unsigned long long b) {
    unsigned long long d;
    asm("add.rn.f32x2 %0, %1, %2;" : "=l"(d) : "l"(a), "l"(b));
    return d;
}
static __device__ __forceinline__ void unpack2_(unsigned long long v, float& lo, float& hi) {
    asm("mov.b64 {%0, %1}, %2;" : "=f"(lo), "=f"(hi) : "l"(v));
}
static __device__ __forceinline__ float wredsum_(float v) {
#pragma unroll
    for (int m = 16; m > 0; m >>= 1) v += __shfl_xor_sync(0xffffffffu, v, m);
    return v;
}

// MAC over this warp's 32-index half (broadcast reads of own shared half),
// accumulating own-state (SO) and foreign-state (SF) partials. 32 FFMA2.
#define MACH(SO, SF)                                                        \
    {                                                                       \
        const ulonglong2* wv_ = (const ulonglong2*)(&wsh[h << 5]);          \
        unsigned long long o0_=0ull, o1_=0ull, f0_=0ull, f1_=0ull;          \
        _Pragma("unroll")                                                   \
        for (int k_ = 0; k_ < 8; k_++) {                                    \
            ulonglong2 q_ = wv_[k_];                                        \
            o0_ = fma2_(q_.x, eO[2*k_],     o0_);                           \
            o1_ = fma2_(q_.y, eO[2*k_ + 1], o1_);                           \
            f0_ = fma2_(q_.x, eF[2*k_],     f0_);                           \
            f1_ = fma2_(q_.y, eF[2*k_ + 1], f1_);                           \
        }                                                                   \
        float lo_, hi_;                                                     \
        unpack2_(addx2_(o0_, o1_), lo_, hi_); SO = lo_ + hi_;               \
        unpack2_(addx2_(f0_, f1_), lo_, hi_); SF = lo_ + hi_;               \
    }

// Forward body (MAC then p). Norm on PB==1 bodies, D = w two bodies back
// (dsh[1], written post-BAR two bodies ago -> race-free pre-BAR read).
#define FBODY(UU, PB)                                                       \
    {                                                                       \
        float pO_;                                                          \
        if (PB) {                                                           \
            float D_ = dsh[1]; float lD_ = lg2f_(D_); loff += lD_;          \
            pO_ = ex2f_(fmaf(pf[UU], LOG2E, -lD_));                         \
        } else {                                                            \
            pO_ = ex2f_(pf[UU] * LOG2E);                                    \
        }                                                                   \
        pf[UU] = *(const float*)(potc + off);                               \
        off = min(off + 256, offhi);                                        \
        float sO_, sF_;                                                     \
        MACH(sO_, sF_)                                                      \
        pp[PB][jF] = sF_;                                                   \
        __syncthreads();                                                    \
        float v_ = (sO_ + pp[PB][jO]) * pO_;                                \
        wsh[jO] = v_;                                                       \
        if (jO == 0) dsh[PB] = v_;                                          \
        __syncwarp();                                                       \
    }

// Backward body (p then MAC). Norm D = y of previous body (dsh[PB^1]).
#define BBODY(UU, PB)                                                       \
    {                                                                       \
        float pO_;                                                          \
        if (PB) {                                                           \
            float D_ = dsh[(PB) ^ 1]; float lD_ = lg2f_(D_); loff += lD_;   \
            pO_ = ex2f_(fmaf(pf[UU], LOG2E, -lD_));                         \
        } else {                                                            \
            pO_ = ex2f_(pf[UU] * LOG2E);                                    \
        }                                                                   \
        pf[UU] = *(const float*)(potc + off);                               \
        off = max(off - 256, offlo);                                        \
        float y_ = x * pO_;                                                 \
        wsh[jO] = y_;                                                       \
        if (jO == 0) dsh[PB] = y_;                                          \
        __syncwarp();                                                       \
        float sO_, sF_;                                                     \
        MACH(sO_, sF_)                                                      \
        pp[PB][jF] = sF_;                                                   \
        __syncthreads();                                                    \
        x = sO_ + pp[PB][jO];                                               \
    }

// One CTA (64 threads, 2 warps) per (batch, task).
// Warp h owns states [32h, 32h+32); lane owns state jO = 32h+lane.
__global__ __launch_bounds__(64, 8) void crf_all_kernel(
    const float* __restrict__ pot,     // [B, T, 64]
    const int*   __restrict__ tags,    // [B, T]
    const int*   __restrict__ seqlen,  // [B]
    const float* __restrict__ K,       // [64, 64]
    const float* __restrict__ sw,      // [B]
    float*       __restrict__ out,
    int T, int B)
{
    const int b    = blockIdx.x / NTASK;
    const int k    = blockIdx.x % NTASK;
    const int tid  = threadIdx.x;
    const int lane = tid & 31;
    const int h    = tid >> 5;
    const int jO   = (h << 5) + lane;          // own state/index
    const int jF   = ((1 - h) << 5) + lane;    // foreign state/index

    int L = seqlen[b];
    if (L > T) L = T;
    if (L < 1) L = 1;
    const int M  = L - 1;
    const int nc = (M + CHUNK - 1) / CHUNK;

    const float* potb = pot + (size_t)b * T * 64;
    const char*  potc = (const char*)potb;

    __shared__ __align__(16) float wsh[64];
    __shared__ float pp[2][64];
    __shared__ float dsh[2];
    __shared__ float sred[64];
    __shared__ int stags[1024];

    if (k == 15) {
        // ================= sequence-score gathers =================
        const int* tagb = tags + (size_t)b * T;
        for (int t = tid; t < T; t += 64) stags[t] = tagb[t];
        __syncthreads();
        float acc = 0.f;
        for (int t = tid; t < T; t += 64) {
            if (t < L) {
                int tg = stags[t];
                acc += __ldg(potb + (size_t)t * 64 + tg);
                if (t >= 1) acc += __ldg(K + stags[t - 1] * 64 + tg);
            }
        }
        sred[tid] = acc;
        __syncthreads();
        if (h == 0) {
            float v = sred[lane] + sred[lane + 32];
            v = wredsum_(v);
            if (lane == 0) g_seqs[b] = v;
        }
    } else {
        const bool is_q = (k < MAXC);
        const int  c    = is_q ? (k + 1) : (k - MAXC + 1);
        const bool valid = is_q ? (c <= nc) : (c <= nc - 1);
        if (!valid) return;    // whole CTA returns; invalid tasks do NOT arrive

        const int a    = (c - 1) * CHUNK + 1;
        const int bend = min(c * CHUNK, M);
        const int ns   = bend - a + 1;
        const int s4   = jO << 2;
        const int offlo = a * 256 + s4;
        const int offhi = bend * 256 + s4;

        // E registers: this warp's 32-index half for own + foreign state.
        unsigned long long eO[16], eF[16];
        if (is_q) {
            // backward: rows jO/jF of E, columns in this warp's j-half
#pragma unroll
            for (int m = 0; m < 16; m++) {
                int c0 = (h << 5) + 2 * m;
                eO[m] = pack2_(ex2f_(K[jO * 64 + c0]     * LOG2E),
                               ex2f_(K[jO * 64 + c0 + 1] * LOG2E));
                eF[m] = pack2_(ex2f_(K[jF * 64 + c0]     * LOG2E),
                               ex2f_(K[jF * 64 + c0 + 1] * LOG2E));
            }
        } else {
            // forward: columns jO/jF of E, rows in this warp's i-half
#pragma unroll
            for (int m = 0; m < 16; m++) {
                int r0 = (h << 5) + 2 * m;
                eO[m] = pack2_(ex2f_(K[r0 * 64 + jO]       * LOG2E),
                               ex2f_(K[(r0 + 1) * 64 + jO] * LOG2E));
                eF[m] = pack2_(ex2f_(K[r0 * 64 + jF]       * LOG2E),
                               ex2f_(K[(r0 + 1) * 64 + jF] * LOG2E));
            }
        }

        float loff = 0.f;
        float pf[4];

        if (is_q) {
            // ---- backward: x = Pi_{t=bend..a} (E diag p_t) applied to 1 ----
            float x = 1.0f;
#pragma unroll
            for (int u = 0; u < 4; u++) {
                int r = bend - u; if (r < a) r = a;
                pf[u] = potb[(size_t)r * 64 + jO];
            }
            int off = (bend - 4) * 256 + s4;
            if (off < offlo) off = offlo;
            __syncthreads();   // (nothing to init; aligns warps before first pp use)

            int n4 = ns >> 2;
            for (int it = 0; it < n4; it++) {
                BBODY(0, 0) BBODY(1, 1) BBODY(2, 0) BBODY(3, 1)
            }
            int rem = ns & 3;
            if (rem > 0) BBODY(0, 0)
            if (rem > 1) BBODY(1, 1)
            if (rem > 2) BBODY(2, 0)

            g_qv[b][c - 1][jO] = x;
            if (tid == 0) g_qoff[b][c - 1] = loff;
        } else {
            // ---- forward: r^T = 1^T Pi_{t=a..bend} (E diag p_t) ----
            wsh[jO] = 1.0f;
            if (tid == 0) { dsh[0] = 1.0f; dsh[1] = 1.0f; }
#pragma unroll
            for (int u = 0; u < 4; u++) {
                int r = a + u; if (r > bend) r = bend;
                pf[u] = potb[(size_t)r * 64 + jO];
            }
            int off = (a + 4) * 256 + s4;
            if (off > offhi) off = offhi;
            __syncthreads();

            int n4 = ns >> 2;
            for (int it = 0; it < n4; it++) {
                FBODY(0, 0) FBODY(1, 1) FBODY(2, 0) FBODY(3, 1)
            }
            int rem = ns & 3;
            if (rem > 0) FBODY(0, 0)
            if (rem > 1) FBODY(1, 1)
            if (rem > 2) FBODY(2, 0)

            g_rv[b][c - 1][jO] = wsh[jO];
            if (tid == 0) g_roff[b][c - 1] = loff;
        }
    }

    // ================= arrival + inline stitch (last task of batch) =================
    __threadfence();
    __syncthreads();      // both warps' global stores fenced before arrival
    if (h != 0) return;

    unsigned int old = 0;
    if (lane == 0) old = atomicAdd(&g_done[b], 1);
    old = __shfl_sync(0xffffffffu, old, 0);
    const unsigned int ntasks = 1u + (unsigned)nc + (unsigned)(nc > 0 ? nc - 1 : 0);
    if (old != ntasks - 1) return;

    if (lane == 0) g_done[b] = 0;    // reset for graph replay
    __threadfence();

    float p0lo = ex2f_(potb[lane] * LOG2E);
    float p0hi = ex2f_(potb[lane + 32] * LOG2E);

    float log2A;
    if (nc == 0) {
        log2A = lg2f_(wredsum_(p0lo + p0hi));
    } else {
        float d1 = wredsum_(p0lo * g_qv[b][0][lane] + p0hi * g_qv[b][0][lane + 32]);
        log2A = lg2f_(d1) + g_qoff[b][0];
        for (int cc = 2; cc <= nc; cc++) {
            float d = wredsum_(g_rv[b][cc-2][lane]      * g_qv[b][cc-1][lane] +
                               g_rv[b][cc-2][lane + 32] * g_qv[b][cc-1][lane + 32]);
            float sig = wredsum_(g_qv[b][cc-2][lane] + g_qv[b][cc-2][lane + 32]);
            log2A += lg2f_(d) + g_roff[b][cc-2] + g_qoff[b][cc-1]
                   - lg2f_(sig) - g_qoff[b][cc-2];
        }
    }

    if (lane == 0) {
        g_partial[b] = -(g_seqs[b] - log2A * LN2) * sw[b];
        __threadfence();
    }
    __syncwarp();

    unsigned int o2 = 0;
    if (lane == 0) o2 = atomicAdd(&g_count, 1);
    o2 = __shfl_sync(0xffffffffu, o2, 0);
    if (o2 == (unsigned)B - 1) {
        if (lane == 0) { g_count = 0; __threadfence(); }
        __syncwarp();
        float tot = 0.f;
        for (int i = lane; i < B; i += 32) tot += g_partial[i];
        tot = wredsum_(tot);
        if (lane == 0) *out = tot / (float)B;
    }
}

extern "C" void kernel_launch(void* const* d_in, const int* in_sizes, int n_in,
                              void* d_out, int out_size) {
    const float* pot    = (const float*)d_in[0];
    const int*   tags   = (const int*)d_in[1];
    const int*   seqlen = (const int*)d_in[2];
    const float* K      = (const float*)d_in[3];
    const float* sw     = (const float*)d_in[4];

    int B = in_sizes[2];            // sequence_length element count
    int T = in_sizes[1] / B;        // tags is [B, T]

    crf_all_kernel<<<B * NTASK, 64>>>(pot, tags, seqlen, K, sw, (float*)d_out, T, B);
}

// round 10
// speedup vs baseline: 1.1518x; 1.1129x over previous
#include <cuda_runtime.h>

#define LOG2E 1.4426950408889634f
#define LN2   0.6931471805599453f
#define CHUNK 64
#define MAXC  16         // ceil(1023/64)
#define NTASK 32         // 0..15 = q (backward), 16..30 = r (forward), 31 = gathers

__device__ float g_qv[1024][MAXC][64];
__device__ float g_rv[1024][MAXC - 1][64];
__device__ float g_qoff[1024][MAXC];
__device__ float g_roff[1024][MAXC - 1];
__device__ float g_seqs[1024];
__device__ float g_partial[1024];
__device__ unsigned int g_done[1024];   // zero-init; self-resetting
__device__ unsigned int g_count = 0;

static __device__ __forceinline__ float ex2f_(float x) {
    float y; asm("ex2.approx.ftz.f32 %0, %1;" : "=f"(y) : "f"(x)); return y;
}
static __device__ __forceinline__ float lg2f_(float x) {
    float y; asm("lg2.approx.ftz.f32 %0, %1;" : "=f"(y) : "f"(x)); return y;
}
static __device__ __forceinline__ unsigned long long pack2_(float lo, float hi) {
    unsigned long long d;
    asm("mov.b64 %0, {%1, %2};" : "=l"(d) : "f"(lo), "f"(hi));
    return d;
}
static __device__ __forceinline__ unsigned long long fma2_(unsigned long long a,
                                                           unsigned long long b,
                                                           unsigned long long c) {
    unsigned long long d;
    asm("fma.rn.f32x2 %0, %1, %2, %3;" : "=l"(d) : "l"(a), "l"(b), "l"(c));
    return d;
}
static __device__ __forceinline__ unsigned long long addx2_(unsigned long long a,
                                                            unsigned long long b) {
    unsigned long long d;
    asm("add.rn.f32x2 %0, %1, %2;" : "=l"(d) : "l"(a), "l"(b));
    return d;
}
static __device__ __forceinline__ void unpack2_(unsigned long long v, float& lo, float& hi) {
    asm("mov.b64 {%0, %1}, %2;" : "=f"(lo), "=f"(hi) : "l"(v));
}
static __device__ __forceinline__ float wredsum_(float v) {
#pragma unroll
    for (int m = 16; m > 0; m >>= 1) v += __shfl_xor_sync(0xffffffffu, v, m);
    return v;
}

// MAC over this warp's 32-index half (broadcast reads of own shared half),
// accumulating own-state (SO) and foreign-state (SF) partials. 32 FFMA2.
#define MACH(SO, SF)                                                        \
    {                                                                       \
        const ulonglong2* wv_ = (const ulonglong2*)(&wsh[h << 5]);          \
        unsigned long long o0_=0ull, o1_=0ull, f0_=0ull, f1_=0ull;          \
        _Pragma("unroll")                                                   \
        for (int k_ = 0; k_ < 8; k_++) {                                    \
            ulonglong2 q_ = wv_[k_];                                        \
            o0_ = fma2_(q_.x, eO[2*k_],     o0_);                           \
            o1_ = fma2_(q_.y, eO[2*k_ + 1], o1_);                           \
            f0_ = fma2_(q_.x, eF[2*k_],     f0_);                           \
            f1_ = fma2_(q_.y, eF[2*k_ + 1], f1_);                           \
        }                                                                   \
        float lo_, hi_;                                                     \
        unpack2_(addx2_(o0_, o1_), lo_, hi_); SO = lo_ + hi_;               \
        unpack2_(addx2_(f0_, f1_), lo_, hi_); SF = lo_ + hi_;               \
    }

// Forward body (MAC then p). Norm on PB==1 bodies, D = w two bodies back
// (dsh[1], written post-BAR two bodies ago -> race-free pre-BAR read).
#define FBODY(UU, PB)                                                       \
    {                                                                       \
        float pO_;                                                          \
        if (PB) {                                                           \
            float D_ = dsh[1]; float lD_ = lg2f_(D_); loff += lD_;          \
            pO_ = ex2f_(fmaf(pf[UU], LOG2E, -lD_));                         \
        } else {                                                            \
            pO_ = ex2f_(pf[UU] * LOG2E);                                    \
        }                                                                   \
        pf[UU] = *(const float*)(potc + off);                               \
        off = min(off + 256, offhi);                                        \
        float sO_, sF_;                                                     \
        MACH(sO_, sF_)                                                      \
        pp[PB][jF] = sF_;                                                   \
        __syncthreads();                                                    \
        float v_ = (sO_ + pp[PB][jO]) * pO_;                                \
        wsh[jO] = v_;                                                       \
        if (jO == 0) dsh[PB] = v_;                                          \
        __syncwarp();                                                       \
    }

// Backward body (p then MAC). Norm D = y of previous body (dsh[PB^1]).
#define BBODY(UU, PB)                                                       \
    {                                                                       \
        float pO_;                                                          \
        if (PB) {                                                           \
            float D_ = dsh[(PB) ^ 1]; float lD_ = lg2f_(D_); loff += lD_;   \
            pO_ = ex2f_(fmaf(pf[UU], LOG2E, -lD_));                         \
        } else {                                                            \
            pO_ = ex2f_(pf[UU] * LOG2E);                                    \
        }                                                                   \
        pf[UU] = *(const float*)(potc + off);                               \
        off = max(off - 256, offlo);                                        \
        float y_ = x * pO_;                                                 \
        wsh[jO] = y_;                                                       \
        if (jO == 0) dsh[PB] = y_;                                          \
        __syncwarp();                                                       \
        float sO_, sF_;                                                     \
        MACH(sO_, sF_)                                                      \
        pp[PB][jF] = sF_;                                                   \
        __syncthreads();                                                    \
        x = sO_ + pp[PB][jO];                                               \
    }

// One CTA (64 threads, 2 warps) per (batch, task).
// Warp h owns states [32h, 32h+32); lane owns state jO = 32h+lane.
__global__ __launch_bounds__(64, 8) void crf_all_kernel(
    const float* __restrict__ pot,     // [B, T, 64]
    const int*   __restrict__ tags,    // [B, T]
    const int*   __restrict__ seqlen,  // [B]
    const float* __restrict__ K,       // [64, 64]
    const float* __restrict__ sw,      // [B]
    float*       __restrict__ out,
    int T, int B)
{
    const int b    = blockIdx.x / NTASK;
    const int k    = blockIdx.x % NTASK;
    const int tid  = threadIdx.x;
    const int lane = tid & 31;
    const int h    = tid >> 5;
    const int jO   = (h << 5) + lane;          // own state/index
    const int jF   = ((1 - h) << 5) + lane;    // foreign state/index

    int L = seqlen[b];
    if (L > T) L = T;
    if (L < 1) L = 1;
    const int M  = L - 1;
    const int nc = (M + CHUNK - 1) / CHUNK;

    const float* potb = pot + (size_t)b * T * 64;
    const char*  potc = (const char*)potb;

    __shared__ __align__(16) float wsh[64];
    __shared__ float pp[2][64];
    __shared__ float dsh[2];
    __shared__ float sred[64];
    __shared__ int stags[1024];

    if (k == NTASK - 1) {
        // ================= sequence-score gathers =================
        const int* tagb = tags + (size_t)b * T;
        for (int t = tid; t < T; t += 64) stags[t] = tagb[t];
        __syncthreads();
        float acc = 0.f;
        for (int t = tid; t < T; t += 64) {
            if (t < L) {
                int tg = stags[t];
                acc += __ldg(potb + (size_t)t * 64 + tg);
                if (t >= 1) acc += __ldg(K + stags[t - 1] * 64 + tg);
            }
        }
        sred[tid] = acc;
        __syncthreads();
        if (h == 0) {
            float v = sred[lane] + sred[lane + 32];
            v = wredsum_(v);
            if (lane == 0) g_seqs[b] = v;
        }
    } else {
        const bool is_q = (k < MAXC);
        const int  c    = is_q ? (k + 1) : (k - MAXC + 1);
        const bool valid = is_q ? (c <= nc) : (c <= nc - 1);
        if (!valid) return;    // whole CTA returns; invalid tasks do NOT arrive

        const int a    = (c - 1) * CHUNK + 1;
        const int bend = min(c * CHUNK, M);
        const int ns   = bend - a + 1;
        const int s4   = jO << 2;
        const int offlo = a * 256 + s4;
        const int offhi = bend * 256 + s4;

        // E registers: this warp's 32-index half for own + foreign state.
        unsigned long long eO[16], eF[16];
        if (is_q) {
            // backward: rows jO/jF of E, columns in this warp's j-half (vectorized)
            const float4* krO = (const float4*)(K + jO * 64 + (h << 5));
            const float4* krF = (const float4*)(K + jF * 64 + (h << 5));
#pragma unroll
            for (int m = 0; m < 8; m++) {
                float4 vO = krO[m], vF = krF[m];
                eO[2*m]   = pack2_(ex2f_(vO.x * LOG2E), ex2f_(vO.y * LOG2E));
                eO[2*m+1] = pack2_(ex2f_(vO.z * LOG2E), ex2f_(vO.w * LOG2E));
                eF[2*m]   = pack2_(ex2f_(vF.x * LOG2E), ex2f_(vF.y * LOG2E));
                eF[2*m+1] = pack2_(ex2f_(vF.z * LOG2E), ex2f_(vF.w * LOG2E));
            }
        } else {
            // forward: columns jO/jF of E, rows in this warp's i-half
#pragma unroll
            for (int m = 0; m < 16; m++) {
                int r0 = (h << 5) + 2 * m;
                eO[m] = pack2_(ex2f_(K[r0 * 64 + jO]       * LOG2E),
                               ex2f_(K[(r0 + 1) * 64 + jO] * LOG2E));
                eF[m] = pack2_(ex2f_(K[r0 * 64 + jF]       * LOG2E),
                               ex2f_(K[(r0 + 1) * 64 + jF] * LOG2E));
            }
        }

        float loff = 0.f;
        float pf[4];

        if (is_q) {
            // ---- backward: x = Pi_{t=bend..a} (E diag p_t) applied to 1 ----
            float x = 1.0f;
#pragma unroll
            for (int u = 0; u < 4; u++) {
                int r = bend - u; if (r < a) r = a;
                pf[u] = potb[(size_t)r * 64 + jO];
            }
            int off = (bend - 4) * 256 + s4;
            if (off < offlo) off = offlo;
            __syncthreads();

            int n4 = ns >> 2;
            for (int it = 0; it < n4; it++) {
                BBODY(0, 0) BBODY(1, 1) BBODY(2, 0) BBODY(3, 1)
            }
            int rem = ns & 3;
            if (rem > 0) BBODY(0, 0)
            if (rem > 1) BBODY(1, 1)
            if (rem > 2) BBODY(2, 0)

            g_qv[b][c - 1][jO] = x;
            if (tid == 0) g_qoff[b][c - 1] = loff;
        } else {
            // ---- forward: r^T = 1^T Pi_{t=a..bend} (E diag p_t) ----
            wsh[jO] = 1.0f;
            if (tid == 0) { dsh[0] = 1.0f; dsh[1] = 1.0f; }
#pragma unroll
            for (int u = 0; u < 4; u++) {
                int r = a + u; if (r > bend) r = bend;
                pf[u] = potb[(size_t)r * 64 + jO];
            }
            int off = (a + 4) * 256 + s4;
            if (off > offhi) off = offhi;
            __syncthreads();

            int n4 = ns >> 2;
            for (int it = 0; it < n4; it++) {
                FBODY(0, 0) FBODY(1, 1) FBODY(2, 0) FBODY(3, 1)
            }
            int rem = ns & 3;
            if (rem > 0) FBODY(0, 0)
            if (rem > 1) FBODY(1, 1)
            if (rem > 2) FBODY(2, 0)

            g_rv[b][c - 1][jO] = wsh[jO];
            if (tid == 0) g_roff[b][c - 1] = loff;
        }
    }

    // ================= arrival + inline stitch (last task of batch) =================
    __threadfence();
    __syncthreads();      // both warps' global stores fenced before arrival
    if (h != 0) return;

    unsigned int old = 0;
    if (lane == 0) old = atomicAdd(&g_done[b], 1);
    old = __shfl_sync(0xffffffffu, old, 0);
    const unsigned int ntasks = 1u + (unsigned)nc + (unsigned)(nc > 0 ? nc - 1 : 0);
    if (old != ntasks - 1) return;

    if (lane == 0) g_done[b] = 0;    // reset for graph replay
    __threadfence();

    float p0lo = ex2f_(potb[lane] * LOG2E);
    float p0hi = ex2f_(potb[lane + 32] * LOG2E);

    float log2A;
    if (nc == 0) {
        log2A = lg2f_(wredsum_(p0lo + p0hi));
    } else {
        float d1 = wredsum_(p0lo * g_qv[b][0][lane] + p0hi * g_qv[b][0][lane + 32]);
        log2A = lg2f_(d1) + g_qoff[b][0];
        for (int cc = 2; cc <= nc; cc++) {
            float d = wredsum_(g_rv[b][cc-2][lane]      * g_qv[b][cc-1][lane] +
                               g_rv[b][cc-2][lane + 32] * g_qv[b][cc-1][lane + 32]);
            float sig = wredsum_(g_qv[b][cc-2][lane] + g_qv[b][cc-2][lane + 32]);
            log2A += lg2f_(d) + g_roff[b][cc-2] + g_qoff[b][cc-1]
                   - lg2f_(sig) - g_qoff[b][cc-2];
        }
    }

    if (lane == 0) {
        g_partial[b] = -(g_seqs[b] - log2A * LN2) * sw[b];
        __threadfence();
    }
    __syncwarp();

    unsigned int o2 = 0;
    if (lane == 0) o2 = atomicAdd(&g_count, 1);
    o2 = __shfl_sync(0xffffffffu, o2, 0);
    if (o2 == (unsigned)B - 1) {
        if (lane == 0) { g_count = 0; __threadfence(); }
        __syncwarp();
        float tot = 0.f;
        for (int i = lane; i < B; i += 32) tot += g_partial[i];
        tot = wredsum_(tot);
        if (lane == 0) *out = tot / (float)B;
    }
}

extern "C" void kernel_launch(void* const* d_in, const int* in_sizes, int n_in,
                              void* d_out, int out_size) {
    const float* pot    = (const float*)d_in[0];
    const int*   tags   = (const int*)d_in[1];
    const int*   seqlen = (const int*)d_in[2];
    const float* K      = (const float*)d_in[3];
    const float* sw     = (const float*)d_in[4];

    int B = in_sizes[2];            // sequence_length element count
    int T = in_sizes[1] / B;        // tags is [B, T]

    crf_all_kernel<<<B * NTASK, 64>>>(pot, tags, seqlen, K, sw, (float*)d_out, T, B);
}

// round 11
// speedup vs baseline: 1.2157x; 1.0555x over previous
#include <cuda_runtime.h>

#define LOG2E 1.4426950408889634f
#define LN2   0.6931471805599453f
#define CHUNK 64
#define MAXC  16         // ceil(1023/64)
#define NPK   17         // per batch: 8 q-pairs, 8 r-pairs, 1 gather

__device__ float g_qv[1024][MAXC][64];
__device__ float g_rv[1024][MAXC - 1][64];
__device__ float g_qoff[1024][MAXC];
__device__ float g_roff[1024][MAXC - 1];
__device__ float g_seqs[1024];
__device__ float g_partial[1024];
__device__ unsigned int g_done[1024];   // zero-init; self-resetting
__device__ unsigned int g_count = 0;

static __device__ __forceinline__ float ex2f_(float x) {
    float y; asm("ex2.approx.ftz.f32 %0, %1;" : "=f"(y) : "f"(x)); return y;
}
static __device__ __forceinline__ float lg2f_(float x) {
    float y; asm("lg2.approx.ftz.f32 %0, %1;" : "=f"(y) : "f"(x)); return y;
}
static __device__ __forceinline__ unsigned long long pack2_(float lo, float hi) {
    unsigned long long d;
    asm("mov.b64 %0, {%1, %2};" : "=l"(d) : "f"(lo), "f"(hi));
    return d;
}
static __device__ __forceinline__ unsigned long long fma2_(unsigned long long a,
                                                           unsigned long long b,
                                                           unsigned long long c) {
    unsigned long long d;
    asm("fma.rn.f32x2 %0, %1, %2, %3;" : "=l"(d) : "l"(a), "l"(b), "l"(c));
    return d;
}
static __device__ __forceinline__ unsigned long long addx2_(unsigned long long a,
                                                            unsigned long long b) {
    unsigned long long d;
    asm("add.rn.f32x2 %0, %1, %2;" : "=l"(d) : "l"(a), "l"(b));
    return d;
}
static __device__ __forceinline__ void unpack2_(unsigned long long v, float& lo, float& hi) {
    asm("mov.b64 {%0, %1}, %2;" : "=f"(lo), "=f"(hi) : "l"(v));
}
static __device__ __forceinline__ float wredsum_(float v) {
#pragma unroll
    for (int m = 16; m > 0; m >>= 1) v += __shfl_xor_sync(0xffffffffu, v, m);
    return v;
}

// Half-contraction over this warp's 32-index half of BUF for states jO and jF.
#define MACHP(BUF, SO, SF)                                                  \
    {                                                                       \
        const ulonglong2* wv_ = (const ulonglong2*)(BUF);                   \
        unsigned long long o0_=0ull, o1_=0ull, f0_=0ull, f1_=0ull;          \
        _Pragma("unroll")                                                   \
        for (int k_ = 0; k_ < 8; k_++) {                                    \
            ulonglong2 q_ = wv_[k_];                                        \
            o0_ = fma2_(q_.x, eO[2*k_],     o0_);                           \
            o1_ = fma2_(q_.y, eO[2*k_ + 1], o1_);                           \
            f0_ = fma2_(q_.x, eF[2*k_],     f0_);                           \
            f1_ = fma2_(q_.y, eF[2*k_ + 1], f1_);                           \
        }                                                                   \
        float lo_, hi_;                                                     \
        unpack2_(addx2_(o0_, o1_), lo_, hi_); SO = lo_ + hi_;               \
        unpack2_(addx2_(f0_, f1_), lo_, hi_); SF = lo_ + hi_;               \
    }

// ---------- paired bodies (two same-orientation chains, one barrier) ----------
#define BPAIR(UU, PB)                                                       \
    {                                                                       \
        float pA_, pB_;                                                     \
        if (PB) {                                                           \
            float DA_ = dshA[(PB)^1]; float lA_ = lg2f_(DA_); loffA += lA_; \
            pA_ = ex2f_(fmaf(pfA[UU], LOG2E, -lA_));                        \
            float DB_ = dshB[(PB)^1]; float lB_ = lg2f_(DB_); loffB += lB_; \
            pB_ = ex2f_(fmaf(pfB[UU], LOG2E, -lB_));                        \
        } else {                                                            \
            pA_ = ex2f_(pfA[UU] * LOG2E);                                   \
            pB_ = ex2f_(pfB[UU] * LOG2E);                                   \
        }                                                                   \
        pfA[UU] = *(const float*)(potc + offA); offA = max(offA-256, offloA);\
        pfB[UU] = *(const float*)(potc + offB); offB = max(offB-256, offloB);\
        float yA_ = xA * pA_, yB_ = xB * pB_;                               \
        wshA[jO] = yA_; wshB[jO] = yB_;                                     \
        if (jO == 0) { dshA[PB] = yA_; dshB[PB] = yB_; }                    \
        __syncwarp();                                                       \
        float sOA_, sFA_, sOB_, sFB_;                                       \
        MACHP(&wshA[h << 5], sOA_, sFA_)                                    \
        MACHP(&wshB[h << 5], sOB_, sFB_)                                    \
        ppA[PB][jF] = sFA_; ppB[PB][jF] = sFB_;                             \
        __syncthreads();                                                    \
        xA = sOA_ + ppA[PB][jO]; xB = sOB_ + ppB[PB][jO];                   \
    }

#define FPAIR(UU, PB)                                                       \
    {                                                                       \
        float pA_, pB_;                                                     \
        if (PB) {                                                           \
            float DA_ = dshA[1]; float lA_ = lg2f_(DA_); loffA += lA_;      \
            pA_ = ex2f_(fmaf(pfA[UU], LOG2E, -lA_));                        \
            float DB_ = dshB[1]; float lB_ = lg2f_(DB_); loffB += lB_;      \
            pB_ = ex2f_(fmaf(pfB[UU], LOG2E, -lB_));                        \
        } else {                                                            \
            pA_ = ex2f_(pfA[UU] * LOG2E);                                   \
            pB_ = ex2f_(pfB[UU] * LOG2E);                                   \
        }                                                                   \
        pfA[UU] = *(const float*)(potc + offA); offA = min(offA+256, offhiA);\
        pfB[UU] = *(const float*)(potc + offB); offB = min(offB+256, offhiB);\
        float sOA_, sFA_, sOB_, sFB_;                                       \
        MACHP(&wshA[h << 5], sOA_, sFA_)                                    \
        MACHP(&wshB[h << 5], sOB_, sFB_)                                    \
        ppA[PB][jF] = sFA_; ppB[PB][jF] = sFB_;                             \
        __syncthreads();                                                    \
        float vA_ = (sOA_ + ppA[PB][jO]) * pA_;                             \
        float vB_ = (sOB_ + ppB[PB][jO]) * pB_;                             \
        wshA[jO] = vA_; wshB[jO] = vB_;                                     \
        if (jO == 0) { dshA[PB] = vA_; dshB[PB] = vB_; }                    \
        __syncwarp();                                                       \
    }

// ---------- single-chain bodies (chain A only; parity-normed) ----------
#define BSING(UU, PB)                                                       \
    {                                                                       \
        float pA_;                                                          \
        if (PB) {                                                           \
            float D_ = dshA[(PB)^1]; float lD_ = lg2f_(D_); loffA += lD_;   \
            pA_ = ex2f_(fmaf(pfA[UU], LOG2E, -lD_));                        \
        } else {                                                            \
            pA_ = ex2f_(pfA[UU] * LOG2E);                                   \
        }                                                                   \
        pfA[UU] = *(const float*)(potc + offA); offA = max(offA-256, offloA);\
        float y_ = xA * pA_;                                                \
        wshA[jO] = y_;                                                      \
        if (jO == 0) dshA[PB] = y_;                                         \
        __syncwarp();                                                       \
        float sO_, sF_;                                                     \
        MACHP(&wshA[h << 5], sO_, sF_)                                      \
        ppA[PB][jF] = sF_;                                                  \
        __syncthreads();                                                    \
        xA = sO_ + ppA[PB][jO];                                             \
    }

#define FSING(UU, PB)                                                       \
    {                                                                       \
        float pA_;                                                          \
        if (PB) {                                                           \
            float D_ = dshA[1]; float lD_ = lg2f_(D_); loffA += lD_;        \
            pA_ = ex2f_(fmaf(pfA[UU], LOG2E, -lD_));                        \
        } else {                                                            \
            pA_ = ex2f_(pfA[UU] * LOG2E);                                   \
        }                                                                   \
        pfA[UU] = *(const float*)(potc + offA); offA = min(offA+256, offhiA);\
        float sO_, sF_;                                                     \
        MACHP(&wshA[h << 5], sO_, sF_)                                      \
        ppA[PB][jF] = sF_;                                                  \
        __syncthreads();                                                    \
        float v_ = (sO_ + ppA[PB][jO]) * pA_;                               \
        wshA[jO] = v_;                                                      \
        if (jO == 0) dshA[PB] = v_;                                         \
        __syncwarp();                                                       \
    }

// ---------- tail bodies (chain A, always-norm, ping-ponged slots via tp) ----------
#define BTAIL(TQ)                                                           \
    {                                                                       \
        float D_ = dshA[tp ^ 1]; float lD_ = lg2f_(D_); loffA += lD_;       \
        float p_ = ex2f_(fmaf(TQ, LOG2E, -lD_));                            \
        TQ = *(const float*)(potc + offT); offT = max(offT-256, offloA);    \
        float y_ = xA * p_;                                                 \
        wshA[jO] = y_;                                                      \
        if (jO == 0) dshA[tp] = y_;                                         \
        __syncwarp();                                                       \
        float sO_, sF_;                                                     \
        MACHP(&wshA[h << 5], sO_, sF_)                                      \
        ppA[tp][jF] = sF_;                                                  \
        __syncthreads();                                                    \
        xA = sO_ + ppA[tp][jO];                                             \
        tp ^= 1;                                                            \
    }

#define FTAIL(TQ)                                                           \
    {                                                                       \
        float D_ = dshA[tp ^ 1]; float lD_ = lg2f_(D_); loffA += lD_;       \
        float p_ = ex2f_(fmaf(TQ, LOG2E, -lD_));                            \
        TQ = *(const float*)(potc + offT); offT = min(offT+256, offhiA);    \
        float sO_, sF_;                                                     \
        MACHP(&wshA[h << 5], sO_, sF_)                                      \
        ppA[tp][jF] = sF_;                                                  \
        __syncthreads();                                                    \
        float v_ = (sO_ + ppA[tp][jO]) * p_;                                \
        wshA[jO] = v_;                                                      \
        if (jO == 0) dshA[tp] = v_;                                         \
        __syncwarp();                                                       \
        tp ^= 1;                                                            \
    }

// One CTA (64 threads, 2 warps) per (batch, task-pair).
__global__ __launch_bounds__(64, 8) void crf_all_kernel(
    const float* __restrict__ pot,     // [B, T, 64]
    const int*   __restrict__ tags,    // [B, T]
    const int*   __restrict__ seqlen,  // [B]
    const float* __restrict__ K,       // [64, 64]
    const float* __restrict__ sw,      // [B]
    float*       __restrict__ out,
    int T, int B)
{
    const int b    = blockIdx.x / NPK;
    const int k    = blockIdx.x % NPK;
    const int tid  = threadIdx.x;
    const int lane = tid & 31;
    const int h    = tid >> 5;
    const int jO   = (h << 5) + lane;
    const int jF   = ((1 - h) << 5) + lane;

    int L = seqlen[b];
    if (L > T) L = T;
    if (L < 1) L = 1;
    const int M  = L - 1;
    const int nc = (M + CHUNK - 1) / CHUNK;

    const float* potb = pot + (size_t)b * T * 64;
    const char*  potc = (const char*)potb;

    __shared__ __align__(16) float wshA[64];
    __shared__ __align__(16) float wshB[64];
    __shared__ float ppA[2][64], ppB[2][64];
    __shared__ float dshA[2], dshB[2];
    __shared__ float sred[64];
    __shared__ int stags[1024];

    int cnt = 1;

    if (k == NPK - 1) {
        // ================= sequence-score gathers =================
        const int* tagb = tags + (size_t)b * T;
        for (int t = tid; t < T; t += 64) stags[t] = tagb[t];
        __syncthreads();
        float acc = 0.f;
        for (int t = tid; t < T; t += 64) {
            if (t < L) {
                int tg = stags[t];
                acc += __ldg(potb + (size_t)t * 64 + tg);
                if (t >= 1) acc += __ldg(K + stags[t - 1] * 64 + tg);
            }
        }
        sred[tid] = acc;
        __syncthreads();
        if (h == 0) {
            float v = sred[lane] + sred[lane + 32];
            v = wredsum_(v);
            if (lane == 0) g_seqs[b] = v;
        }
    } else {
        const bool is_q = (k < 8);
        const int  kp   = is_q ? k : (k - 8);
        const int  cA   = 2 * kp + 1;
        const int  cB   = 2 * kp + 2;
        const int  cmax = is_q ? nc : (nc - 1);
        const bool validA = (cA <= cmax);
        const bool validB = (cB <= cmax);
        if (!validA) return;          // no arrival
        cnt = validB ? 2 : 1;

        const int aA = (cA - 1) * CHUNK + 1, bendA = min(cA * CHUNK, M);
        const int aB = (cB - 1) * CHUNK + 1, bendB = min(cB * CHUNK, M);
        const int nsA = bendA - aA + 1;
        const int nsB = validB ? (bendB - aB + 1) : 0;
        const int s4 = jO << 2;
        const int offloA = aA * 256 + s4, offhiA = bendA * 256 + s4;
        const int offloB = aB * 256 + s4, offhiB = bendB * 256 + s4;

        // E registers: shared by both chains (same orientation).
        unsigned long long eO[16], eF[16];
        if (is_q) {
            const float4* krO = (const float4*)(K + jO * 64 + (h << 5));
            const float4* krF = (const float4*)(K + jF * 64 + (h << 5));
#pragma unroll
            for (int m = 0; m < 8; m++) {
                float4 vO = krO[m], vF = krF[m];
                eO[2*m]   = pack2_(ex2f_(vO.x * LOG2E), ex2f_(vO.y * LOG2E));
                eO[2*m+1] = pack2_(ex2f_(vO.z * LOG2E), ex2f_(vO.w * LOG2E));
                eF[2*m]   = pack2_(ex2f_(vF.x * LOG2E), ex2f_(vF.y * LOG2E));
                eF[2*m+1] = pack2_(ex2f_(vF.z * LOG2E), ex2f_(vF.w * LOG2E));
            }
        } else {
#pragma unroll
            for (int m = 0; m < 16; m++) {
                int r0 = (h << 5) + 2 * m;
                eO[m] = pack2_(ex2f_(K[r0 * 64 + jO]       * LOG2E),
                               ex2f_(K[(r0 + 1) * 64 + jO] * LOG2E));
                eF[m] = pack2_(ex2f_(K[r0 * 64 + jF]       * LOG2E),
                               ex2f_(K[(r0 + 1) * 64 + jF] * LOG2E));
            }
        }

        float loffA = 0.f, loffB = 0.f;
        float pfA[4], pfB[4];
        int tp = 0;

        if (tid == 0) { dshA[0] = dshA[1] = 1.0f; dshB[0] = dshB[1] = 1.0f; }

        if (is_q) {
            // ======== backward chains ========
            float xA = 1.0f, xB = 1.0f;
#pragma unroll
            for (int u = 0; u < 4; u++) {
                int rA = bendA - u; if (rA < aA) rA = aA;
                pfA[u] = potb[(size_t)rA * 64 + jO];
                int rB = validB ? (bendB - u) : aA;
                if (rB < aB) rB = aB;
                pfB[u] = validB ? potb[(size_t)rB * 64 + jO] : 0.f;
            }
            int offA = (bendA - 4) * 256 + s4; if (offA < offloA) offA = offloA;
            int offB = validB ? ((bendB - 4) * 256 + s4) : offloB;
            if (offB < offloB) offB = offloB;
            __syncthreads();

            if (validB) {
                int n4 = nsB >> 2;
                for (int it = 0; it < n4; it++) {
                    BPAIR(0, 0) BPAIR(1, 1) BPAIR(2, 0) BPAIR(3, 1)
                }
                int rem = nsB & 3;
                if (rem > 0) BPAIR(0, 0)
                if (rem > 1) BPAIR(1, 1)
                if (rem > 2) BPAIR(2, 0)

                g_qv[b][cB - 1][jO] = xB;
                if (tid == 0) g_qoff[b][cB - 1] = loffB;

                // tail for A: remaining nsA - nsB bodies (A always full here)
                int rem2 = nsA - nsB;
                if (rem2 > 0) {
                    int tn = bendA - nsB;
                    int r0 = tn, r1 = tn - 1;
                    if (r1 < aA) r1 = aA;
                    float tq0 = potb[(size_t)r0 * 64 + jO];
                    float tq1 = potb[(size_t)r1 * 64 + jO];
                    int offT = (tn - 2) * 256 + s4; if (offT < offloA) offT = offloA;
                    int s = 0;
                    for (; s + 2 <= rem2; s += 2) { BTAIL(tq0) BTAIL(tq1) }
                    if (s < rem2) BTAIL(tq0)
                }
            } else {
                int n4 = nsA >> 2;
                for (int it = 0; it < n4; it++) {
                    BSING(0, 0) BSING(1, 1) BSING(2, 0) BSING(3, 1)
                }
                int rem = nsA & 3;
                if (rem > 0) BSING(0, 0)
                if (rem > 1) BSING(1, 1)
                if (rem > 2) BSING(2, 0)
            }

            g_qv[b][cA - 1][jO] = xA;
            if (tid == 0) g_qoff[b][cA - 1] = loffA;
        } else {
            // ======== forward chains ========
            wshA[jO] = 1.0f; wshB[jO] = 1.0f;
#pragma unroll
            for (int u = 0; u < 4; u++) {
                int rA = aA + u; if (rA > bendA) rA = bendA;
                pfA[u] = potb[(size_t)rA * 64 + jO];
                int rB = aB + u; if (rB > bendB) rB = bendB;
                pfB[u] = validB ? potb[(size_t)rB * 64 + jO] : 0.f;
            }
            int offA = (aA + 4) * 256 + s4; if (offA > offhiA) offA = offhiA;
            int offB = validB ? ((aB + 4) * 256 + s4) : offloB;
            if (offB > offhiB) offB = offhiB;
            __syncthreads();

            if (validB) {
                int n4 = nsB >> 2;
                for (int it = 0; it < n4; it++) {
                    FPAIR(0, 0) FPAIR(1, 1) FPAIR(2, 0) FPAIR(3, 1)
                }
                int rem = nsB & 3;
                if (rem > 0) FPAIR(0, 0)
                if (rem > 1) FPAIR(1, 1)
                if (rem > 2) FPAIR(2, 0)

                g_rv[b][cB - 1][jO] = wshB[jO];
                if (tid == 0) g_roff[b][cB - 1] = loffB;

                int rem2 = nsA - nsB;
                if (rem2 > 0) {
                    int tn = aA + nsB;
                    int r0 = tn, r1 = tn + 1;
                    if (r1 > bendA) r1 = bendA;
                    float tq0 = potb[(size_t)r0 * 64 + jO];
                    float tq1 = potb[(size_t)r1 * 64 + jO];
                    int offT = (tn + 2) * 256 + s4; if (offT > offhiA) offT = offhiA;
                    int s = 0;
                    for (; s + 2 <= rem2; s += 2) { FTAIL(tq0) FTAIL(tq1) }
                    if (s < rem2) FTAIL(tq0)
                }
            } else {
                int n4 = nsA >> 2;
                for (int it = 0; it < n4; it++) {
                    FSING(0, 0) FSING(1, 1) FSING(2, 0) FSING(3, 1)
                }
                int rem = nsA & 3;
                if (rem > 0) FSING(0, 0)
                if (rem > 1) FSING(1, 1)
                if (rem > 2) FSING(2, 0)
            }

            g_rv[b][cA - 1][jO] = wshA[jO];
            if (tid == 0) g_roff[b][cA - 1] = loffA;
        }
    }

    // ================= arrival + inline stitch (last task of batch) =================
    __threadfence();
    __syncthreads();
    if (h != 0) return;

    const unsigned int ntasks = 1u + (unsigned)nc + (unsigned)(nc > 0 ? nc - 1 : 0);
    unsigned int old = 0;
    if (lane == 0) old = atomicAdd(&g_done[b], (unsigned)cnt);
    old = __shfl_sync(0xffffffffu, old, 0);
    if (old + (unsigned)cnt != ntasks) return;

    if (lane == 0) g_done[b] = 0;    // reset for graph replay
    __threadfence();

    float p0lo = ex2f_(potb[lane] * LOG2E);
    float p0hi = ex2f_(potb[lane + 32] * LOG2E);

    float log2A;
    if (nc == 0) {
        log2A = lg2f_(wredsum_(p0lo + p0hi));
    } else {
        float d1 = wredsum_(p0lo * g_qv[b][0][lane] + p0hi * g_qv[b][0][lane + 32]);
        log2A = lg2f_(d1) + g_qoff[b][0];
        for (int cc = 2; cc <= nc; cc++) {
            float d = wredsum_(g_rv[b][cc-2][lane]      * g_qv[b][cc-1][lane] +
                               g_rv[b][cc-2][lane + 32] * g_qv[b][cc-1][lane + 32]);
            float sig = wredsum_(g_qv[b][cc-2][lane] + g_qv[b][cc-2][lane + 32]);
            log2A += lg2f_(d) + g_roff[b][cc-2] + g_qoff[b][cc-1]
                   - lg2f_(sig) - g_qoff[b][cc-2];
        }
    }

    if (lane == 0) {
        g_partial[b] = -(g_seqs[b] - log2A * LN2) * sw[b];
        __threadfence();
    }
    __syncwarp();

    unsigned int o2 = 0;
    if (lane == 0) o2 = atomicAdd(&g_count, 1);
    o2 = __shfl_sync(0xffffffffu, o2, 0);
    if (o2 == (unsigned)B - 1) {
        if (lane == 0) { g_count = 0; __threadfence(); }
        __syncwarp();
        float tot = 0.f;
        for (int i = lane; i < B; i += 32) tot += g_partial[i];
        tot = wredsum_(tot);
        if (lane == 0) *out = tot / (float)B;
    }
}

extern "C" void kernel_launch(void* const* d_in, const int* in_sizes, int n_in,
                              void* d_out, int out_size) {
    const float* pot    = (const float*)d_in[0];
    const int*   tags   = (const int*)d_in[1];
    const int*   seqlen = (const int*)d_in[2];
    const float* K      = (const float*)d_in[3];
    const float* sw     = (const float*)d_in[4];

    int B = in_sizes[2];            // sequence_length element count
    int T = in_sizes[1] / B;        // tags is [B, T]

    crf_all_kernel<<<B * NPK, 64>>>(pot, tags, seqlen, K, sw, (float*)d_out, T, B);
}